// round 3
// baseline (speedup 1.0000x reference)
#include <cuda_runtime.h>
#include <cuda_bf16.h>
#include <math.h>

// ---------------- problem constants ----------------
#define NMAX 10000
#define EMAX 320000
#define MMAX (EMAX + NMAX)   // edges + self loops

// ---------------- device scratch (no allocs allowed; referenced directly in kernels) ----------------
__device__ __align__(16) float g_H0 [NMAX * 512];   // x @ W0^T
__device__ __align__(16) float g_H0A[NMAX * 512];   // elu(agg0 + b0)
__device__ __align__(16) float g_H1 [NMAX * 128];   // H0A @ W1^T
__device__ __align__(16) float g_H1A[NMAX * 128];   // elu(agg1 + b1)
__device__ __align__(16) float g_H2 [NMAX * 128];   // H1A @ Wout^T + bout
__device__ __align__(16) float g_AS0[NMAX * 4];
__device__ __align__(16) float g_AD0[NMAX * 4];
__device__ __align__(16) float g_AS1[NMAX];
__device__ __align__(16) float g_AD1[NMAX];
__device__ __align__(16) float g_S1 [NMAX];
__device__ __align__(16) float g_S2 [NMAX];
__device__ __align__(16) int   g_deg[NMAX];
__device__ __align__(16) int   g_off[NMAX + 1];
__device__ __align__(16) int   g_cur[NMAX];
__device__ __align__(16) int   g_srt[MMAX];

// buffer ids for generic kernels
#define B_H0   0
#define B_H0A  1
#define B_H1   2
#define B_H1A  3
#define B_H2   4
#define B_AS0  5
#define B_AD0  6
#define B_AS1  7
#define B_AD1  8
#define B_S1   9
#define B_S2   10
#define B_EXT  (-1)

__device__ __forceinline__ float* buf_sel(int id) {
    switch (id) {
        case B_H0:  return g_H0;
        case B_H0A: return g_H0A;
        case B_H1:  return g_H1;
        case B_H1A: return g_H1A;
        case B_H2:  return g_H2;
        case B_AS0: return g_AS0;
        case B_AD0: return g_AD0;
        case B_AS1: return g_AS1;
        case B_AD1: return g_AD1;
        case B_S1:  return g_S1;
        default:    return g_S2;
    }
}

// ---------------- CSR build kernels ----------------
__global__ void zero_deg_kernel(int n) {
    int i = blockIdx.x * blockDim.x + threadIdx.x;
    if (i < n) g_deg[i] = 0;
}

// edge_index is int32 (JAX silently downcasts int64 -> int32 without x64 mode)
__global__ void hist_kernel(const int* __restrict__ ei, int E, int n) {
    int e = blockIdx.x * blockDim.x + threadIdx.x;
    int M = E + n;
    if (e >= M) return;
    int dst = (e < E) ? ei[E + e] : (e - E);
    if ((unsigned)dst < (unsigned)n)   // defensive: never trap on bad input parse
        atomicAdd(&g_deg[dst], 1);
}

// single block, 1024 threads: exclusive scan of deg -> off (and cur copy)
__global__ void scan_kernel(int n) {
    __shared__ int sm[1024];
    int t = threadIdx.x;
    int chunk = (n + 1023) >> 10;
    int b = t * chunk;
    int e = min(n, b + chunk);
    int s = 0;
    for (int i = b; i < e; i++) s += g_deg[i];
    sm[t] = s;
    __syncthreads();
    for (int o = 1; o < 1024; o <<= 1) {
        int v = (t >= o) ? sm[t - o] : 0;
        __syncthreads();
        sm[t] += v;
        __syncthreads();
    }
    int run = sm[t] - s;   // exclusive base
    for (int i = b; i < e; i++) {
        g_off[i] = run;
        g_cur[i] = run;
        run += g_deg[i];
    }
    if (t == 1023) g_off[n] = sm[1023];
}

__global__ void scatter_kernel(const int* __restrict__ ei, int E, int n) {
    int e = blockIdx.x * blockDim.x + threadIdx.x;
    int M = E + n;
    if (e >= M) return;
    int src, dst;
    if (e < E) { src = ei[e]; dst = ei[E + e]; }
    else       { src = e - E; dst = e - E; }
    if ((unsigned)dst >= (unsigned)n || (unsigned)src >= (unsigned)n) return;
    int pos = atomicAdd(&g_cur[dst], 1);
    if (pos < MMAX) g_srt[pos] = src;
}

// ---------------- generic fp32 GEMM: C[M,N] = A[M,K] * B[N,K]^T (+bias) ----------------
#define BM 64
#define BN 64
#define BK 16
__global__ void gemm_abt_kernel(const float* __restrict__ Aext, int aid,
                                const float* __restrict__ B,
                                const float* __restrict__ bias,
                                int cid, int M, int N, int K) {
    const float* A = (aid == B_EXT) ? Aext : buf_sel(aid);
    float* C = buf_sel(cid);

    __shared__ float As[BK][BM + 4];
    __shared__ float Bs[BK][BN + 4];
    int tid = threadIdx.x;          // 256
    int tx = tid & 15;              // 0..15
    int ty = tid >> 4;              // 0..15
    int lk = tid & 15;              // k within tile
    int lr = tid >> 4;              // row within 16-group
    int bm = blockIdx.y * BM;
    int bn = blockIdx.x * BN;

    float acc[4][4] = {};

    for (int k0 = 0; k0 < K; k0 += BK) {
#pragma unroll
        for (int i = 0; i < 4; i++) {
            int r = bm + lr + 16 * i;
            As[lk][lr + 16 * i] = (r < M) ? A[(size_t)r * K + k0 + lk] : 0.f;
            int rb = bn + lr + 16 * i;     // always < N (N multiple of 64)
            Bs[lk][lr + 16 * i] = B[(size_t)rb * K + k0 + lk];
        }
        __syncthreads();
#pragma unroll
        for (int kk = 0; kk < BK; kk++) {
            float4 a = *(const float4*)&As[kk][ty * 4];
            float4 b = *(const float4*)&Bs[kk][tx * 4];
            acc[0][0] += a.x * b.x; acc[0][1] += a.x * b.y; acc[0][2] += a.x * b.z; acc[0][3] += a.x * b.w;
            acc[1][0] += a.y * b.x; acc[1][1] += a.y * b.y; acc[1][2] += a.y * b.z; acc[1][3] += a.y * b.w;
            acc[2][0] += a.z * b.x; acc[2][1] += a.z * b.y; acc[2][2] += a.z * b.z; acc[2][3] += a.z * b.w;
            acc[3][0] += a.w * b.x; acc[3][1] += a.w * b.y; acc[3][2] += a.w * b.z; acc[3][3] += a.w * b.w;
        }
        __syncthreads();
    }

#pragma unroll
    for (int i = 0; i < 4; i++) {
        int row = bm + ty * 4 + i;
        if (row >= M) continue;
        int col = bn + tx * 4;
        float4 o;
        o.x = acc[i][0]; o.y = acc[i][1]; o.z = acc[i][2]; o.w = acc[i][3];
        if (bias) {
            o.x += bias[col + 0]; o.y += bias[col + 1];
            o.z += bias[col + 2]; o.w += bias[col + 3];
        }
        *(float4*)&C[(size_t)row * N + col] = o;
    }
}

// ---------------- attention coefficients: out[n,h] = sum_c H[n,h,c]*att[h,c] ----------------
__global__ void attn_coef_kernel(int hid, const float* __restrict__ atts,
                                 const float* __restrict__ attd,
                                 int osid, int odid, int heads) {
    const float* H = buf_sel(hid);
    float* osrc = buf_sel(osid);
    float* odst = buf_sel(odid);

    int node = blockIdx.x;
    int t = threadIdx.x;            // 128
    int w = t >> 5, lane = t & 31;
    int Ct = heads * 128;
    float ps[4] = {0.f, 0.f, 0.f, 0.f}, pd[4] = {0.f, 0.f, 0.f, 0.f};
    for (int k = 0; k < heads; k++) {
        float h = H[(size_t)node * Ct + k * 128 + t];
        ps[k] = h * atts[k * 128 + t];
        pd[k] = h * attd[k * 128 + t];
    }
#pragma unroll
    for (int o = 16; o; o >>= 1) {
#pragma unroll
        for (int k = 0; k < 4; k++) {
            ps[k] += __shfl_xor_sync(~0u, ps[k], o);
            pd[k] += __shfl_xor_sync(~0u, pd[k], o);
        }
    }
    __shared__ float ss[4][4], sd[4][4];
    if (lane == 0) {
#pragma unroll
        for (int k = 0; k < 4; k++) { ss[w][k] = ps[k]; sd[w][k] = pd[k]; }
    }
    __syncthreads();
    if (t < heads) {
        osrc[node * heads + t] = ss[0][t] + ss[1][t] + ss[2][t] + ss[3][t];
        odst[node * heads + t] = sd[0][t] + sd[1][t] + sd[2][t] + sd[3][t];
    }
}

// ---------------- layer-0 aggregation: 4 heads x 128 ch, block=128 per node ----------------
__global__ void agg0_kernel(const float* __restrict__ b0) {
    int node = blockIdx.x;
    int t = threadIdx.x;            // 128
    int w = t >> 5, lane = t & 31;
    int beg = g_off[node], end = g_off[node + 1];

    float adsth = g_AD0[node * 4 + w];

    // pass 1: per-head max (lanes stride edges)
    float m = -1e30f;
    for (int i = beg + lane; i < end; i += 32) {
        int s = g_srt[i];
        float a = g_AS0[s * 4 + w] + adsth;
        a = (a >= 0.f) ? a : 0.2f * a;
        m = fmaxf(m, a);
    }
#pragma unroll
    for (int o = 16; o; o >>= 1) m = fmaxf(m, __shfl_xor_sync(~0u, m, o));
    __shared__ float mx[4];
    if (lane == 0) mx[w] = m;
    __syncthreads();
    float mh = mx[w];

    // pass 2: accumulate sum(ex * h) and sum(ex)
    float4 acc = {0.f, 0.f, 0.f, 0.f};
    float denom = 0.f;
    for (int i = beg; i < end; i++) {
        int s = g_srt[i];
        float a = g_AS0[s * 4 + w] + adsth;
        a = (a >= 0.f) ? a : 0.2f * a;
        float ex = __expf(a - mh);
        denom += ex;
        float4 v = *(const float4*)&g_H0[(size_t)s * 512 + t * 4];
        acc.x += ex * v.x; acc.y += ex * v.y; acc.z += ex * v.z; acc.w += ex * v.w;
    }
    float inv = 1.f / (denom + 1e-16f);
    float4 bb = *(const float4*)&b0[t * 4];
    float4 o4;
    o4.x = acc.x * inv + bb.x;
    o4.y = acc.y * inv + bb.y;
    o4.z = acc.z * inv + bb.z;
    o4.w = acc.w * inv + bb.w;
    // elu
    o4.x = (o4.x > 0.f) ? o4.x : expm1f(o4.x);
    o4.y = (o4.y > 0.f) ? o4.y : expm1f(o4.y);
    o4.z = (o4.z > 0.f) ? o4.z : expm1f(o4.z);
    o4.w = (o4.w > 0.f) ? o4.w : expm1f(o4.w);
    *(float4*)&g_H0A[(size_t)node * 512 + t * 4] = o4;
}

// ---------------- layer-1 aggregation: 1 head x 128 ch, warp per node ----------------
__global__ void agg1_kernel(const float* __restrict__ b1, int n) {
    int w = threadIdx.x >> 5, lane = threadIdx.x & 31;
    int node = blockIdx.x * 4 + w;
    if (node >= n) return;
    int beg = g_off[node], end = g_off[node + 1];
    float adv = g_AD1[node];

    float m = -1e30f;
    for (int i = beg + lane; i < end; i += 32) {
        float a = g_AS1[g_srt[i]] + adv;
        a = (a >= 0.f) ? a : 0.2f * a;
        m = fmaxf(m, a);
    }
#pragma unroll
    for (int o = 16; o; o >>= 1) m = fmaxf(m, __shfl_xor_sync(~0u, m, o));
    // m now lane-uniform

    float4 acc = {0.f, 0.f, 0.f, 0.f};
    float denom = 0.f;
    for (int i = beg; i < end; i++) {
        int s = g_srt[i];
        float a = g_AS1[s] + adv;
        a = (a >= 0.f) ? a : 0.2f * a;
        float ex = __expf(a - m);
        denom += ex;
        float4 v = *(const float4*)&g_H1[(size_t)s * 128 + lane * 4];
        acc.x += ex * v.x; acc.y += ex * v.y; acc.z += ex * v.z; acc.w += ex * v.w;
    }
    float inv = 1.f / (denom + 1e-16f);
    float4 bb = *(const float4*)&b1[lane * 4];
    float4 o4;
    o4.x = acc.x * inv + bb.x;
    o4.y = acc.y * inv + bb.y;
    o4.z = acc.z * inv + bb.z;
    o4.w = acc.w * inv + bb.w;
    o4.x = (o4.x > 0.f) ? o4.x : expm1f(o4.x);
    o4.y = (o4.y > 0.f) ? o4.y : expm1f(o4.y);
    o4.z = (o4.z > 0.f) ? o4.z : expm1f(o4.z);
    o4.w = (o4.w > 0.f) ? o4.w : expm1f(o4.w);
    *(float4*)&g_H1A[(size_t)node * 128 + lane * 4] = o4;
}

// ---------------- final outer sum: out[i*n+j] = s1[i] + s2[j] + bedge ----------------
__global__ void outer_kernel(const float* __restrict__ bedge, float* __restrict__ out, int n) {
    int i = blockIdx.x;
    float v = g_S1[i] + bedge[0];
    float* row = out + (size_t)i * n;
    int n4 = n >> 2;
    const float4* s24 = (const float4*)g_S2;
    for (int j = threadIdx.x; j < n4; j += blockDim.x) {
        float4 b = s24[j];
        float4 o = {v + b.x, v + b.y, v + b.z, v + b.w};
        ((float4*)row)[j] = o;
    }
    for (int j = (n4 << 2) + threadIdx.x; j < n; j += blockDim.x)
        row[j] = v + g_S2[j];
}

// ---------------- host launcher (kernel launches ONLY) ----------------
extern "C" void kernel_launch(void* const* d_in, const int* in_sizes, int n_in,
                              void* d_out, int out_size) {
    const float* x        = (const float*)d_in[0];
    const int*   ei       = (const int*)d_in[1];     // int32 (JAX x64 disabled)
    const float* W0       = (const float*)d_in[2];
    const float* att_src0 = (const float*)d_in[3];
    const float* att_dst0 = (const float*)d_in[4];
    const float* b0       = (const float*)d_in[5];
    const float* W1       = (const float*)d_in[6];
    const float* att_src1 = (const float*)d_in[7];
    const float* att_dst1 = (const float*)d_in[8];
    const float* b1       = (const float*)d_in[9];
    const float* Wout     = (const float*)d_in[10];
    const float* bout     = (const float*)d_in[11];
    const float* Wedge    = (const float*)d_in[12];
    const float* bedge    = (const float*)d_in[13];
    float* out = (float*)d_out;

    int n = in_sizes[0] / 128;
    int E = in_sizes[1] / 2;
    int M = E + n;

    // ---- CSR build (counting sort by dst) ----
    zero_deg_kernel<<<(n + 255) / 256, 256>>>(n);
    hist_kernel<<<(M + 255) / 256, 256>>>(ei, E, n);
    scan_kernel<<<1, 1024>>>(n);
    scatter_kernel<<<(M + 255) / 256, 256>>>(ei, E, n);

    // ---- layer 0: H0 = x @ W0^T ----
    {
        dim3 grid(512 / BN, (n + BM - 1) / BM);
        gemm_abt_kernel<<<grid, 256>>>(x, B_EXT, W0, nullptr, B_H0, n, 512, 128);
    }
    attn_coef_kernel<<<n, 128>>>(B_H0, att_src0, att_dst0, B_AS0, B_AD0, 4);
    agg0_kernel<<<n, 128>>>(b0);

    // ---- layer 1: H1 = H0A @ W1^T ----
    {
        dim3 grid(128 / BN, (n + BM - 1) / BM);
        gemm_abt_kernel<<<grid, 256>>>(nullptr, B_H0A, W1, nullptr, B_H1, n, 128, 512);
    }
    attn_coef_kernel<<<n, 128>>>(B_H1, att_src1, att_dst1, B_AS1, B_AD1, 1);
    agg1_kernel<<<(n + 3) / 4, 128>>>(b1, n);

    // ---- output projection: H2 = H1A @ Wout^T + bout ----
    {
        dim3 grid(128 / BN, (n + BM - 1) / BM);
        gemm_abt_kernel<<<grid, 256>>>(nullptr, B_H1A, Wout, bout, B_H2, n, 128, 128);
    }

    // ---- edge scores s1 = H2 @ w1, s2 = H2 @ w2 (attn_coef with heads=1) ----
    attn_coef_kernel<<<n, 128>>>(B_H2, Wedge, Wedge + 128, B_S1, B_S2, 1);

    // ---- final n x n outer sum ----
    outer_kernel<<<n, 256>>>(bedge, out, n);
}